// round 16
// baseline (speedup 1.0000x reference)
#include <cuda_runtime.h>
#include <cuda_fp16.h>
#include <cstdint>

// Fused 9-layer MLP, weight-stationary restructure (R15).
// One kernel per layer: grid 296 (1 CTA/SM, each CTA owns a 128-col n-half),
// layer weights staged ONCE into smem, activation row-tiles (64 rows) streamed
// via cp.async double buffer from global fp16 ping-pong buffers.
// mma.sync fp16 HMMA, fp32 accum. Numerics identical to R10-R14 (~7.6e-5).

#define THREADS 256
#define NROWS   262144
#define NTILES  4096          // 64-row tiles

// ---- device-global scratch (static; no allocation) ----
__device__ __align__(256) __half g_w[30 * 16384];       // 30 chunks [64k][256n]
__device__ __align__(256) __half g_x[NROWS * 64];       // padded fp16 input
__device__ __align__(256) __half g_act0[NROWS * 256];   // ping
__device__ __align__(256) __half g_act1[NROWS * 256];   // pong

// ---- smem layout (bytes) ----
#define WSTR2   272                    // W row stride (128 cols * 2B -> pad)
#define SM_WB   0                      // W: 320 rows x 272 = 87040
#define SM_BI   87040                  // bias: 128 fp32 = 512
#define SM_AT   87552                  // A tiles: 2 x 64x528 = 67584
#define ABUF_SZ (64 * 528)
#define SM_XT   155136                 // X tiles: 2 x 64x144 = 18432
#define XBUF_SZ (64 * 144)
#define SM_TOTAL 173568

#define ASTR 528
#define XSTR 144

// ---------- PTX helpers ----------
__device__ __forceinline__ uint32_t smem_u32(const void* p) {
    uint32_t a;
    asm("{ .reg .u64 t; cvta.to.shared.u64 t, %1; cvt.u32.u64 %0, t; }" : "=r"(a) : "l"(p));
    return a;
}
__device__ __forceinline__ void cpa16(uint8_t* s, const uint8_t* g) {
    uint32_t ss = smem_u32(s);
    asm volatile("cp.async.cg.shared.global [%0], [%1], 16;" :: "r"(ss), "l"(g));
}
__device__ __forceinline__ void cp_commit() { asm volatile("cp.async.commit_group;"); }
__device__ __forceinline__ void cp_wait0()  { asm volatile("cp.async.wait_group 0;"); }

__device__ __forceinline__ void ldsm4(uint32_t* r, uint32_t addr) {
    asm volatile("ldmatrix.sync.aligned.m8n8.x4.shared.b16 {%0,%1,%2,%3}, [%4];"
                 : "=r"(r[0]), "=r"(r[1]), "=r"(r[2]), "=r"(r[3]) : "r"(addr));
}
__device__ __forceinline__ void ldsm4t(uint32_t* r, uint32_t addr) {
    asm volatile("ldmatrix.sync.aligned.m8n8.x4.trans.shared.b16 {%0,%1,%2,%3}, [%4];"
                 : "=r"(r[0]), "=r"(r[1]), "=r"(r[2]), "=r"(r[3]) : "r"(addr));
}
__device__ __forceinline__ void mma_f16(float* c, const uint32_t* a, uint32_t b0, uint32_t b1) {
    asm volatile(
        "mma.sync.aligned.m16n8k16.row.col.f32.f16.f16.f32 "
        "{%0,%1,%2,%3}, {%4,%5,%6,%7}, {%8,%9}, {%0,%1,%2,%3};"
        : "+f"(c[0]), "+f"(c[1]), "+f"(c[2]), "+f"(c[3])
        : "r"(a[0]), "r"(a[1]), "r"(a[2]), "r"(a[3]), "r"(b0), "r"(b1));
}
__device__ __forceinline__ uint32_t pack_h2(float v0, float v1) {
    __half h0 = __float2half_rn(v0);
    __half h1 = __float2half_rn(v1);
    return ((uint32_t)__half_as_ushort(h1) << 16) | __half_as_ushort(h0);
}

__device__ __forceinline__ __half* actbuf(int s) {
    return s == 0 ? g_act0 : (s == 1 ? g_act1 : g_x);
}

// ---------- prep: fp32 weights -> fp16 [k][n] chunks ----------
__global__ void __launch_bounds__(256) prep_kernel(
    const float* __restrict__ w1, const float* __restrict__ w2,
    const float* __restrict__ w3, const float* __restrict__ w4,
    const float* __restrict__ w5, const float* __restrict__ w6,
    const float* __restrict__ w7, const float* __restrict__ w8)
{
    int gid = blockIdx.x * 256 + threadIdx.x;   // 0 .. 491519
    int chunk = gid >> 14;
    int e = gid & 16383;
    int kl = e >> 8;
    int r  = e & 255;
    const float* src; int k0, Ksrc;
    if (chunk == 0)      { src = w1; k0 = 0;                 Ksrc = 39;  }
    else if (chunk < 5)  { src = w2; k0 = (chunk - 1) * 64;  Ksrc = 256; }
    else if (chunk < 9)  { src = w3; k0 = (chunk - 5) * 64;  Ksrc = 256; }
    else if (chunk < 13) { src = w4; k0 = (chunk - 9) * 64;  Ksrc = 256; }
    else if (chunk < 18) { src = w5; k0 = (chunk - 13) * 64; Ksrc = 295; }
    else if (chunk < 22) { src = w6; k0 = (chunk - 18) * 64; Ksrc = 256; }
    else if (chunk < 26) { src = w7; k0 = (chunk - 22) * 64; Ksrc = 256; }
    else                 { src = w8; k0 = (chunk - 26) * 64; Ksrc = 256; }
    int k = k0 + kl;
    float v = (k < Ksrc) ? src[k * 256 + r] : 0.0f;
    g_w[gid] = __float2half_rn(v);
}

// ---------- prep: x fp32 [N][39] -> g_x fp16 [N][64] padded ----------
__global__ void __launch_bounds__(256) prep_x_kernel(const float* __restrict__ x)
{
    for (int gid = blockIdx.x * 256 + threadIdx.x; gid < NROWS * 64;
         gid += gridDim.x * 256) {
        int row = gid >> 6, k = gid & 63;
        g_x[gid] = __float2half_rn((k < 39) ? x[(size_t)row * 39 + k] : 0.0f);
    }
}

// ---------- generic layer kernel (weight-stationary) ----------
// C = relu(A[Kin] @ W (+ X @ Wx) + bias), fp16 out.  nkc in {1,4}; hasX adds
// 64 more W rows (rows nkc*64 .. +63) multiplying the x tile.
__global__ void __launch_bounds__(THREADS, 1) layer_kernel(
    int asel, int astride, int nkc, int wcb, int hasX,
    const float* __restrict__ bias, int osel)
{
    extern __shared__ uint8_t sm[];
    const int tid  = threadIdx.x;
    const int wid  = tid >> 5;
    const int lane = tid & 31;
    const int nhalf  = blockIdx.x & 1;
    const int stripe = blockIdx.x >> 1;
    const int row0w = (wid & 1) * 32;      // warp m-offset within 64-row tile
    const int col0w = (wid >> 1) * 32;     // warp n-offset within 128-col half

    const __half* A   = actbuf(asel);
    __half*       out = actbuf(osel);
    float* bsm = (float*)(sm + SM_BI);
    const uint32_t w_base = smem_u32(sm + SM_WB);
    const uint32_t a_base = smem_u32(sm + SM_AT);
    const uint32_t x_base = smem_u32(sm + SM_XT);

    const int Kin  = nkc * 64;
    const int rcpS = (nkc == 1) ? 3 : 5;           // log2(cpa16 per A row)
    const int Wrows = nkc * 64 + (hasX ? 64 : 0);

    // ---- stage W (once) + bias ----
    for (int i = tid; i < Wrows * 16; i += THREADS) {
        int row = i >> 4, j = i & 15;
        const uint8_t* src = (const uint8_t*)(g_w + (wcb + (row >> 6)) * 16384
                                              + (row & 63) * 256 + nhalf * 128);
        cpa16(sm + SM_WB + row * WSTR2 + j * 16, src + j * 16);
    }
    if (tid < 128) bsm[tid] = bias[nhalf * 128 + tid];

    // ---- stage A tile 0 (+ x tile 0) ----
    int t0 = stripe;
    {
        int row0g = t0 * 64;
        int rcp = 1 << rcpS;
        for (int i = tid; i < 64 * rcp; i += THREADS) {
            int row = i >> rcpS, j = i & (rcp - 1);
            cpa16(sm + SM_AT + row * ASTR + j * 16,
                  (const uint8_t*)(A + (size_t)(row0g + row) * astride) + j * 16);
        }
        if (hasX) {
            for (int i = tid; i < 64 * 8; i += THREADS) {
                int row = i >> 3, j = i & 7;
                cpa16(sm + SM_XT + row * XSTR + j * 16,
                      (const uint8_t*)(g_x + (size_t)(row0g + row) * 64) + j * 16);
            }
        }
    }
    cp_commit();
    cp_wait0();
    __syncthreads();

    const int quad = lane >> 3;
    const int qr   = lane & 7;
    const int arow_off = ((quad & 1) << 3) + qr;
    const int acol_off = (quad >> 1) << 3;
    const int brow_off = ((quad & 1) << 3) + qr;
    const int bcol_off = (quad >> 1) << 3;
    const int nks_h = nkc * 4;

    int buf = 0;
    for (int t = stripe; t < NTILES; t += 148) {
        const int tn = t + 148;
        const bool more = (tn < NTILES);
        // prefetch next tile into buf^1 (its old contents consumed pre-sync)
        if (more) {
            int row0g = tn * 64;
            int rcp = 1 << rcpS;
            uint8_t* dst = sm + SM_AT + (buf ^ 1) * ABUF_SZ;
            for (int i = tid; i < 64 * rcp; i += THREADS) {
                int row = i >> rcpS, j = i & (rcp - 1);
                cpa16(dst + row * ASTR + j * 16,
                      (const uint8_t*)(A + (size_t)(row0g + row) * astride) + j * 16);
            }
            if (hasX) {
                uint8_t* xdst = sm + SM_XT + (buf ^ 1) * XBUF_SZ;
                for (int i = tid; i < 64 * 8; i += THREADS) {
                    int row = i >> 3, j = i & 7;
                    cpa16(xdst + row * XSTR + j * 16,
                          (const uint8_t*)(g_x + (size_t)(row0g + row) * 64) + j * 16);
                }
            }
            cp_commit();
        }

        // ---- compute tile t ----
        float C[2][4][4];
#pragma unroll
        for (int i = 0; i < 2; i++)
#pragma unroll
            for (int j = 0; j < 4; j++)
#pragma unroll
                for (int q = 0; q < 4; q++) C[i][j][q] = 0.0f;

        const uint32_t ab = a_base + buf * ABUF_SZ;
        for (int ks = 0; ks < nks_h; ks++) {
            const int k0 = ks * 16;
            uint32_t b[2][4], a[2][4];
#pragma unroll
            for (int np = 0; np < 2; np++) {
                int ncol = col0w + np * 16 + bcol_off;
                ldsm4t(b[np], w_base + (uint32_t)((k0 + brow_off) * WSTR2 + ncol * 2));
            }
#pragma unroll
            for (int mf = 0; mf < 2; mf++) {
                int row = row0w + mf * 16 + arow_off;
                ldsm4(a[mf], ab + (uint32_t)(row * ASTR + (k0 + acol_off) * 2));
            }
#pragma unroll
            for (int mf = 0; mf < 2; mf++)
#pragma unroll
                for (int np = 0; np < 2; np++)
#pragma unroll
                    for (int ns = 0; ns < 2; ns++)
                        mma_f16(C[mf][np * 2 + ns], a[mf], b[np][2 * ns], b[np][2 * ns + 1]);
        }
        if (hasX) {
            const uint32_t xb = x_base + buf * XBUF_SZ;
            const int wr0 = nks_h * 16;    // W rows for x part start here
            for (int ks = 0; ks < 4; ks++) {
                const int k0 = ks * 16;
                uint32_t b[2][4], a[2][4];
#pragma unroll
                for (int np = 0; np < 2; np++) {
                    int ncol = col0w + np * 16 + bcol_off;
                    ldsm4t(b[np], w_base + (uint32_t)((wr0 + k0 + brow_off) * WSTR2 + ncol * 2));
                }
#pragma unroll
                for (int mf = 0; mf < 2; mf++) {
                    int row = row0w + mf * 16 + arow_off;
                    ldsm4(a[mf], xb + (uint32_t)(row * XSTR + (k0 + acol_off) * 2));
                }
#pragma unroll
                for (int mf = 0; mf < 2; mf++)
#pragma unroll
                    for (int np = 0; np < 2; np++)
#pragma unroll
                        for (int ns = 0; ns < 2; ns++)
                            mma_f16(C[mf][np * 2 + ns], a[mf], b[np][2 * ns], b[np][2 * ns + 1]);
            }
        }

        // ---- epilogue: bias + relu -> fp16 STG to global ----
        {
            const int row0g = t * 64;
#pragma unroll
            for (int mf = 0; mf < 2; mf++) {
#pragma unroll
                for (int nf = 0; nf < 4; nf++) {
                    int col = col0w + nf * 8 + 2 * (lane & 3);
                    int rA  = row0w + mf * 16 + (lane >> 2);
                    float* cc = C[mf][nf];
                    float v0 = fmaxf(cc[0] + bsm[col],     0.0f);
                    float v1 = fmaxf(cc[1] + bsm[col + 1], 0.0f);
                    float v2 = fmaxf(cc[2] + bsm[col],     0.0f);
                    float v3 = fmaxf(cc[3] + bsm[col + 1], 0.0f);
                    size_t base0 = (size_t)(row0g + rA) * 256 + nhalf * 128 + col;
                    size_t base1 = base0 + 8 * 256;
                    *(uint32_t*)(out + base0) = pack_h2(v0, v1);
                    *(uint32_t*)(out + base1) = pack_h2(v2, v3);
                }
            }
        }

        if (more) { cp_wait0(); __syncthreads(); }
        buf ^= 1;
    }
}

// ---------- layer 9: out[N][4] = h8 @ w9 + b9 (warp per row) ----------
__global__ void __launch_bounds__(256) layer9_kernel(
    const float* __restrict__ w9, const float* __restrict__ b9,
    float* __restrict__ out)
{
    const int wid  = (blockIdx.x * 256 + threadIdx.x) >> 5;   // global warp id
    const int lane = threadIdx.x & 31;
    const __half* h8 = g_act1;
    const int nwarps = (gridDim.x * 256) >> 5;

    // each lane covers k = lane*8 .. lane*8+7
    float wl[8][4];
#pragma unroll
    for (int j = 0; j < 8; j++)
#pragma unroll
        for (int c = 0; c < 4; c++)
            wl[j][c] = w9[(lane * 8 + j) * 4 + c];

    for (int r = wid; r < NROWS; r += nwarps) {
        uint4 hv = *(const uint4*)(h8 + (size_t)r * 256 + lane * 8);
        __half2 h01 = *(__half2*)&hv.x, h23 = *(__half2*)&hv.y;
        __half2 h45 = *(__half2*)&hv.z, h67 = *(__half2*)&hv.w;
        float h[8] = { __low2float(h01), __high2float(h01),
                       __low2float(h23), __high2float(h23),
                       __low2float(h45), __high2float(h45),
                       __low2float(h67), __high2float(h67) };
        float p0 = 0.f, p1 = 0.f, p2 = 0.f, p3 = 0.f;
#pragma unroll
        for (int j = 0; j < 8; j++) {
            p0 += h[j] * wl[j][0];
            p1 += h[j] * wl[j][1];
            p2 += h[j] * wl[j][2];
            p3 += h[j] * wl[j][3];
        }
#pragma unroll
        for (int o = 16; o > 0; o >>= 1) {
            p0 += __shfl_xor_sync(0xFFFFFFFFu, p0, o);
            p1 += __shfl_xor_sync(0xFFFFFFFFu, p1, o);
            p2 += __shfl_xor_sync(0xFFFFFFFFu, p2, o);
            p3 += __shfl_xor_sync(0xFFFFFFFFu, p3, o);
        }
        if (lane < 4) {
            float v = (lane == 0) ? p0 : (lane == 1) ? p1 : (lane == 2) ? p2 : p3;
            out[(size_t)r * 4 + lane] = v + b9[lane];
        }
    }
}

extern "C" void kernel_launch(void* const* d_in, const int* in_sizes, int n_in,
                              void* d_out, int out_size)
{
    const float* x  = (const float*)d_in[0];
    const float* w1 = (const float*)d_in[1],  *b1 = (const float*)d_in[2];
    const float* w2 = (const float*)d_in[3],  *b2 = (const float*)d_in[4];
    const float* w3 = (const float*)d_in[5],  *b3 = (const float*)d_in[6];
    const float* w4 = (const float*)d_in[7],  *b4 = (const float*)d_in[8];
    const float* w5 = (const float*)d_in[9],  *b5 = (const float*)d_in[10];
    const float* w6 = (const float*)d_in[11], *b6 = (const float*)d_in[12];
    const float* w7 = (const float*)d_in[13], *b7 = (const float*)d_in[14];
    const float* w8 = (const float*)d_in[15], *b8 = (const float*)d_in[16];
    const float* w9 = (const float*)d_in[17], *b9 = (const float*)d_in[18];
    float* out = (float*)d_out;

    prep_kernel<<<1920, 256>>>(w1, w2, w3, w4, w5, w6, w7, w8);
    prep_x_kernel<<<4096, 256>>>(x);

    static bool attr_set = false;
    if (!attr_set) {
        cudaFuncSetAttribute(layer_kernel,
                             cudaFuncAttributeMaxDynamicSharedMemorySize, SM_TOTAL);
        attr_set = true;
    }

    // asel/osel: 0=g_act0, 1=g_act1, 2=g_x
    layer_kernel<<<296, THREADS, SM_TOTAL>>>(2, 64,  1, 0,  0, b1, 0);  // L1: x -> act0
    layer_kernel<<<296, THREADS, SM_TOTAL>>>(0, 256, 4, 1,  0, b2, 1);  // L2
    layer_kernel<<<296, THREADS, SM_TOTAL>>>(1, 256, 4, 5,  0, b3, 0);  // L3
    layer_kernel<<<296, THREADS, SM_TOTAL>>>(0, 256, 4, 9,  0, b4, 1);  // L4
    layer_kernel<<<296, THREADS, SM_TOTAL>>>(1, 256, 4, 13, 1, b5, 0);  // L5 (+x)
    layer_kernel<<<296, THREADS, SM_TOTAL>>>(0, 256, 4, 18, 0, b6, 1);  // L6
    layer_kernel<<<296, THREADS, SM_TOTAL>>>(1, 256, 4, 22, 0, b7, 0);  // L7
    layer_kernel<<<296, THREADS, SM_TOTAL>>>(0, 256, 4, 26, 0, b8, 1);  // L8 -> act1
    layer9_kernel<<<512, 256>>>(w9, b9, out);                           // L9
}